// round 2
// baseline (speedup 1.0000x reference)
#include <cuda_runtime.h>
#include <math.h>

// Problem dimensions (fixed for this dataset)
#define WORD_N   50000
#define QUERY_N  50000
#define ENT_N    100000
#define REV_N    100000
#define EDGE_N   2000000
#define BATCH_N  1024
#define DWDIM    64
#define DDIM     128

// ---------------- scratch (static __device__, no allocation) ----------------
__device__ __align__(16) float g_hq[QUERY_N * DWDIM];    // MHSA(query docs)
__device__ __align__(16) float g_hr[REV_N * DWDIM];      // MHSA(review docs)
__device__ __align__(16) float g_qb[BATCH_N * DWDIM];    // MHSA(batch queries)
__device__ __align__(16) float g_enth[ENT_N * DWDIM];    // summed review embs per entity
__device__ __align__(16) float g_degp[ENT_N];
__device__ __align__(16) float g_degi[ENT_N];
__device__ __align__(16) float g_invs[ENT_N];
__device__ __align__(16) float g_ek[ENT_N * DDIM];       // e_0 = [W_entity | ent_h]
__device__ __align__(16) float g_qe0[QUERY_N * DDIM];    // [W_query | h_query]
__device__ __align__(16) float g_agg[ENT_N * DDIM];      // conv accumulator
__device__ __align__(16) float g_P[4 * 64 * 64];         // P_h = Wv[:,h16] @ Wo[h16,:]

// ---------------- helpers ----------------
__device__ __forceinline__ void red_add_v4(float* p, float4 v) {
    asm volatile("red.global.add.v4.f32 [%0], {%1,%2,%3,%4};"
                 :: "l"(p), "f"(v.x), "f"(v.y), "f"(v.z), "f"(v.w)
                 : "memory");
}

// ---------------- zero scratch ----------------
__global__ void zero_kernel(int N) {
    int g = blockIdx.x * blockDim.x + threadIdx.x;
    int stride = gridDim.x * blockDim.x;
    float4 z = make_float4(0.f, 0.f, 0.f, 0.f);
    int n_agg4 = N * 32;           // N*128/4
    for (int i = g; i < n_agg4; i += stride) ((float4*)g_agg)[i] = z;
    int n_eh4 = N * 16;            // N*64/4
    for (int i = g; i < n_eh4; i += stride) ((float4*)g_enth)[i] = z;
    int n4 = N / 4;
    for (int i = g; i < n4; i += stride) {
        ((float4*)g_degp)[i] = z;
        ((float4*)g_degi)[i] = z;
    }
}

// ---------------- precompute P_h = Wv[:, h*16:(h+1)*16] @ Wo[h*16:(h+1)*16, :] ----------------
__global__ void precompute_P(const float* __restrict__ Wv, const float* __restrict__ Wo) {
    int t = threadIdx.x;
    for (int i = t; i < 4 * 64 * 64; i += blockDim.x) {
        int h = i >> 12;
        int d = (i >> 6) & 63;
        int c = i & 63;
        float s = 0.f;
        #pragma unroll
        for (int u = 0; u < 16; u++)
            s += Wv[d * 64 + h * 16 + u] * Wo[(h * 16 + u) * 64 + c];
        g_P[i] = s;
    }
}

// ---------------- MHSA + mean over all docs (one warp per doc) ----------------
// Algebra: out = sum_h y_h @ P_h,  y_h = sum_j a[h][j] * x[j],
//          a[h][j] = mean_l softmax_j(q_l . k_j / 4)
__global__ __launch_bounds__(256)
void mhsa_kernel(const float* __restrict__ W_word,
                 const float* __restrict__ Wq_g, const float* __restrict__ Wk_g,
                 const int* __restrict__ qids, const int* __restrict__ rids,
                 const int* __restrict__ bids,
                 int Q, int R, int B)
{
    extern __shared__ float smem[];
    float* sWq = smem;              // 4096
    float* sWk = smem + 4096;       // 4096
    float* sx  = smem + 8192;       // 8 warps * 512
    float* sq  = sx + 8 * 512;      // 8 * 512
    float* sk  = sq + 8 * 512;      // 8 * 512
    float* sy  = sk + 8 * 512;      // 8 * 256

    int tid = threadIdx.x;
    for (int i = tid; i < 4096; i += 256) { sWq[i] = Wq_g[i]; sWk[i] = Wk_g[i]; }
    __syncthreads();

    int lane = tid & 31, warp = tid >> 5;
    float* xw = sx + warp * 512;
    float* qw = sq + warp * 512;
    float* kw = sk + warp * 512;
    float* yw = sy + warp * 256;

    int T = Q + R + B;
    int gwarp = blockIdx.x * 8 + warp;
    int nwarp = gridDim.x * 8;
    int c0 = lane * 2;
    int xrow = lane >> 2, xseg = lane & 3;
    int hh = lane >> 3, jj = lane & 7;

    for (int doc = gwarp; doc < T; doc += nwarp) {
        const int* ids; float* outp;
        if (doc < Q)          { ids = qids + doc * 8;        outp = g_hq + (size_t)doc * 64; }
        else if (doc < Q + R) { int r = doc - Q;  ids = rids + r * 8; outp = g_hr + (size_t)r * 64; }
        else                  { int b = doc - Q - R; ids = bids + b * 8; outp = g_qb + (size_t)b * 64; }

        // load x[8][64] : lane -> (row = lane/4, 16-col segment = lane%4)
        int widx = ids[xrow];
        const float4* xsrc = (const float4*)(W_word + (size_t)widx * 64 + xseg * 16);
        float4* xdst = (float4*)(xw + xrow * 64 + xseg * 16);
        xdst[0] = xsrc[0]; xdst[1] = xsrc[1]; xdst[2] = xsrc[2]; xdst[3] = xsrc[3];
        __syncwarp();

        // q,k projection: lane owns 2 output cols for all 8 rows
        float aq0[8], aq1[8], ak0[8], ak1[8];
        #pragma unroll
        for (int l = 0; l < 8; l++) { aq0[l] = aq1[l] = ak0[l] = ak1[l] = 0.f; }
        #pragma unroll 4
        for (int k = 0; k < 64; k++) {
            float2 wq = *(const float2*)(sWq + k * 64 + c0);
            float2 wk = *(const float2*)(sWk + k * 64 + c0);
            #pragma unroll
            for (int l = 0; l < 8; l++) {
                float xv = xw[l * 64 + k];
                aq0[l] += xv * wq.x; aq1[l] += xv * wq.y;
                ak0[l] += xv * wk.x; ak1[l] += xv * wk.y;
            }
        }
        #pragma unroll
        for (int l = 0; l < 8; l++) {
            *(float2*)(qw + l * 64 + c0) = make_float2(aq0[l], aq1[l]);
            *(float2*)(kw + l * 64 + c0) = make_float2(ak0[l], ak1[l]);
        }
        __syncwarp();

        // scores for lane = (head hh, key jj), all query rows l; softmax over j (8-lane groups)
        float kj[16];
        #pragma unroll
        for (int t = 0; t < 4; t++) {
            float4 kv = *(const float4*)(kw + jj * 64 + hh * 16 + t * 4);
            kj[t*4+0] = kv.x; kj[t*4+1] = kv.y; kj[t*4+2] = kv.z; kj[t*4+3] = kv.w;
        }
        float a_acc = 0.f;
        #pragma unroll
        for (int l = 0; l < 8; l++) {
            float s = 0.f;
            #pragma unroll
            for (int t = 0; t < 4; t++) {
                float4 qv = *(const float4*)(qw + l * 64 + hh * 16 + t * 4);
                s += qv.x*kj[t*4+0] + qv.y*kj[t*4+1] + qv.z*kj[t*4+2] + qv.w*kj[t*4+3];
            }
            float e = expf(s * 0.25f);   // 1/sqrt(16)
            float tsum = e;
            tsum += __shfl_xor_sync(0xffffffffu, tsum, 1);
            tsum += __shfl_xor_sync(0xffffffffu, tsum, 2);
            tsum += __shfl_xor_sync(0xffffffffu, tsum, 4);
            a_acc += e / tsum;
        }
        a_acc *= 0.125f;                 // mean over l -> a[hh][jj]

        // y_h[64]: 8-lane head group; this lane handles cols [jj*8, jj*8+8)
        float av[8];
        int base = lane & ~7;
        #pragma unroll
        for (int m = 0; m < 8; m++) av[m] = __shfl_sync(0xffffffffu, a_acc, base + m);
        float y0[8];
        #pragma unroll
        for (int c = 0; c < 8; c++) y0[c] = 0.f;
        #pragma unroll
        for (int m = 0; m < 8; m++) {
            #pragma unroll
            for (int c = 0; c < 8; c++)
                y0[c] += av[m] * xw[m * 64 + jj * 8 + c];
        }
        #pragma unroll
        for (int c = 0; c < 8; c++) yw[hh * 64 + jj * 8 + c] = y0[c];
        __syncwarp();

        // out = sum_h y_h @ P_h ; lane owns cols c0, c0+1
        float o0 = 0.f, o1 = 0.f;
        #pragma unroll
        for (int h2 = 0; h2 < 4; h2++) {
            #pragma unroll 8
            for (int d2 = 0; d2 < 64; d2++) {
                float yv = yw[h2 * 64 + d2];
                float2 p = __ldg((const float2*)(g_P + ((h2 * 64 + d2) * 64) + c0));
                o0 += yv * p.x; o1 += yv * p.y;
            }
        }
        outp[c0] = o0; outp[c0 + 1] = o1;
        __syncwarp();
    }
}

// ---------------- profile aggregation: ent_h += h_review, deg_p += 1 ----------------
__global__ void profile_kernel(const int* __restrict__ pdst, int R) {
    int g = blockIdx.x * blockDim.x + threadIdx.x;
    int r = g >> 4, q = g & 15;
    if (r >= R) return;
    int d = pdst[r];
    float4 v = *(const float4*)(g_hr + (size_t)r * 64 + q * 4);
    red_add_v4(g_enth + (size_t)d * 64 + q * 4, v);
    if (q == 0) atomicAdd(g_degp + d, 1.0f);
}

// ---------------- interaction degree ----------------
__global__ void degi_kernel(const int* __restrict__ ps, const int* __restrict__ pd, int E) {
    int g = blockIdx.x * blockDim.x + threadIdx.x;
    if (g >= E) return;
    atomicAdd(g_degi + ps[g], 1.0f);
    atomicAdd(g_degi + pd[g], 1.0f);
}

// ---------------- build e_0, q_e0, inv_sqrt ----------------
__global__ void build_kernel(const float* __restrict__ W_query,
                             const float* __restrict__ W_entity, int Q, int N) {
    int g = blockIdx.x * blockDim.x + threadIdx.x;
    int n = g >> 5, lane = g & 31;
    if (n >= N) return;
    int c = lane * 4;
    if (lane == 0) g_invs[n] = 1.0f / sqrtf(fmaxf(g_degi[n], 1.0f));
    float4 v;
    if (c < 64) {
        v = *(const float4*)(W_entity + (size_t)n * 64 + c);
    } else {
        float invdp = 1.0f / fmaxf(g_degp[n], 1.0f);
        float4 hv = *(const float4*)(g_enth + (size_t)n * 64 + (c - 64));
        v = make_float4(hv.x * invdp, hv.y * invdp, hv.z * invdp, hv.w * invdp);
    }
    *(float4*)(g_ek + (size_t)n * 128 + c) = v;
    if (n < Q) {
        float4 u;
        if (c < 64) u = *(const float4*)(W_query + (size_t)n * 64 + c);
        else        u = *(const float4*)(g_hq + (size_t)n * 64 + (c - 64));
        *(float4*)(g_qe0 + (size_t)n * 128 + c) = u;
    }
}

// ---------------- edge conv (both directions fused), one warp per edge ----------------
__global__ void edge_kernel(const int* __restrict__ ps, const int* __restrict__ pd,
                            const int* __restrict__ pq, int E) {
    long long g = (long long)blockIdx.x * blockDim.x + threadIdx.x;
    int e = (int)(g >> 5);
    int lane = (int)(g & 31);
    if (e >= E) return;
    int src = ps[e], dst = pd[e], qid = pq[e];
    float iss = g_invs[src];
    float isd = g_invs[dst];
    int c = lane * 4;
    float4 es = *(const float4*)(g_ek + (size_t)src * 128 + c);
    float4 qv = *(const float4*)(g_qe0 + (size_t)qid * 128 + c);
    float4 m = make_float4(es.x + qv.x * iss, es.y + qv.y * iss,
                           es.z + qv.z * iss, es.w + qv.w * iss);
    red_add_v4(g_agg + (size_t)dst * 128 + c, m);
    float4 ed = *(const float4*)(g_ek + (size_t)dst * 128 + c);
    float4 m2 = make_float4(ed.x * isd, ed.y * isd, ed.z * isd, ed.w * isd);
    red_add_v4(g_agg + (size_t)src * 128 + c, m2);
}

// ---------------- output: gather e = (e0 + agg*inv)/2 at users/items/negs ----------------
__global__ void output_kernel(const int* __restrict__ users, const int* __restrict__ items,
                              const int* __restrict__ negs, int B, float* __restrict__ out) {
    int g = blockIdx.x * blockDim.x + threadIdx.x;
    int idx = g >> 5, lane = g & 31;
    if (idx >= 3 * B) return;
    int part = idx / B, b = idx % B;
    int r = (part == 0) ? users[b] : ((part == 1) ? items[b] : negs[b]);
    int c = lane * 4;
    float inv = g_invs[r];
    float4 ev = *(const float4*)(g_ek + (size_t)r * 128 + c);
    float4 av = *(const float4*)(g_agg + (size_t)r * 128 + c);
    float4 v = make_float4((ev.x + av.x * inv) * 0.5f, (ev.y + av.y * inv) * 0.5f,
                           (ev.z + av.z * inv) * 0.5f, (ev.w + av.w * inv) * 0.5f);
    if (part == 0 && c >= 64) {
        float4 qb = *(const float4*)(g_qb + (size_t)b * 64 + (c - 64));
        v.x += qb.x; v.y += qb.y; v.z += qb.z; v.w += qb.w;
    }
    *(float4*)(out + (size_t)idx * 128 + c) = v;
}

// ---------------- launch ----------------
extern "C" void kernel_launch(void* const* d_in, const int* in_sizes, int n_in,
                              void* d_out, int out_size) {
    const float* W_word   = (const float*)d_in[0];
    const float* W_query  = (const float*)d_in[1];
    const float* W_entity = (const float*)d_in[2];
    const float* Wq       = (const float*)d_in[3];
    const float* Wk       = (const float*)d_in[4];
    const float* Wv       = (const float*)d_in[5];
    const float* Wo       = (const float*)d_in[6];
    const int* qids   = (const int*)d_in[7];
    const int* rids   = (const int*)d_in[8];
    const int* pdst   = (const int*)d_in[9];
    const int* p_src  = (const int*)d_in[10];
    const int* p_dst  = (const int*)d_in[11];
    const int* p_qid  = (const int*)d_in[12];
    const int* users  = (const int*)d_in[13];
    const int* items  = (const int*)d_in[14];
    const int* negs   = (const int*)d_in[15];
    const int* qwords = (const int*)d_in[16];

    int Q = in_sizes[1] / 64;
    int N = in_sizes[2] / 64;
    int R = in_sizes[9];
    int E = in_sizes[10];
    int B = in_sizes[13];

    zero_kernel<<<4096, 256>>>(N);
    precompute_P<<<1, 256>>>(Wv, Wo);

    size_t smem_bytes = (size_t)(8192 + 8 * 512 * 3 + 8 * 256) * sizeof(float); // 90112 B
    cudaFuncSetAttribute(mhsa_kernel, cudaFuncAttributeMaxDynamicSharedMemorySize,
                         (int)smem_bytes);
    mhsa_kernel<<<1184, 256, smem_bytes>>>(W_word, Wq, Wk, qids, rids, qwords, Q, R, B);

    profile_kernel<<<(R * 16 + 255) / 256, 256>>>(pdst, R);
    degi_kernel<<<(E + 255) / 256, 256>>>(p_src, p_dst, E);
    build_kernel<<<(N * 32 + 255) / 256, 256>>>(W_query, W_entity, Q, N);

    long long ethreads = (long long)E * 32;
    edge_kernel<<<(int)((ethreads + 255) / 256), 256>>>(p_src, p_dst, p_qid, E);

    output_kernel<<<(3 * B * 32 + 255) / 256, 256>>>(users, items, negs, B, (float*)d_out);
}

// round 3
// speedup vs baseline: 1.0934x; 1.0934x over previous
#include <cuda_runtime.h>
#include <math.h>

// Problem dimensions (fixed for this dataset)
#define WORD_N   50000
#define QUERY_N  50000
#define ENT_N    100000
#define REV_N    100000
#define EDGE_N   2000000
#define BATCH_N  1024
#define DWDIM    64
#define DDIM     128

typedef unsigned long long u64t;

// ---------------- scratch (static __device__, no allocation) ----------------
__device__ __align__(16) float g_hq[QUERY_N * DWDIM];    // MHSA(query docs)
__device__ __align__(16) float g_hr[REV_N * DWDIM];      // MHSA(review docs)
__device__ __align__(16) float g_qb[BATCH_N * DWDIM];    // MHSA(batch queries)
__device__ __align__(16) float g_enth[ENT_N * DWDIM];    // summed review embs per entity
__device__ __align__(16) float g_degp[ENT_N];
__device__ __align__(16) float g_degi[ENT_N];
__device__ __align__(16) float g_invs[ENT_N];
__device__ __align__(16) float g_ek[ENT_N * DDIM];       // e_0 = [W_entity | ent_h]
__device__ __align__(16) float g_qe0[QUERY_N * DDIM];    // [W_query | h_query]
__device__ __align__(16) float g_agg[ENT_N * DDIM];      // conv accumulator
__device__ __align__(16) float g_P[4 * 64 * 64];         // P_h = Wv[:,h16] @ Wo[h16,:]

// ---------------- f32x2 packed-FMA helpers (Blackwell FFMA2) ----------------
__device__ __forceinline__ u64t pack1(float x) {
    u64t r; asm("mov.b64 %0, {%1,%1};" : "=l"(r) : "f"(x)); return r;
}
__device__ __forceinline__ u64t ffma2(u64t a, u64t b, u64t c) {
    u64t d; asm("fma.rn.f32x2 %0, %1, %2, %3;" : "=l"(d) : "l"(a), "l"(b), "l"(c));
    return d;
}
__device__ __forceinline__ void red_add_v4(float* p, float4 v) {
    asm volatile("red.global.add.v4.f32 [%0], {%1,%2,%3,%4};"
                 :: "l"(p), "f"(v.x), "f"(v.y), "f"(v.z), "f"(v.w)
                 : "memory");
}

// ---------------- zero scratch ----------------
__global__ void zero_kernel(int N) {
    int g = blockIdx.x * blockDim.x + threadIdx.x;
    int stride = gridDim.x * blockDim.x;
    float4 z = make_float4(0.f, 0.f, 0.f, 0.f);
    int n_agg4 = N * 32;           // N*128/4
    for (int i = g; i < n_agg4; i += stride) ((float4*)g_agg)[i] = z;
    int n_eh4 = N * 16;            // N*64/4
    for (int i = g; i < n_eh4; i += stride) ((float4*)g_enth)[i] = z;
    int n4 = N / 4;
    for (int i = g; i < n4; i += stride) {
        ((float4*)g_degp)[i] = z;
        ((float4*)g_degi)[i] = z;
    }
}

// ---------------- precompute P_h = Wv[:, h*16:(h+1)*16] @ Wo[h*16:(h+1)*16, :] ----------------
__global__ void precompute_P(const float* __restrict__ Wv, const float* __restrict__ Wo) {
    int t = threadIdx.x;
    for (int i = t; i < 4 * 64 * 64; i += blockDim.x) {
        int h = i >> 12;
        int d = (i >> 6) & 63;
        int c = i & 63;
        float s = 0.f;
        #pragma unroll
        for (int u = 0; u < 16; u++)
            s += Wv[d * 64 + h * 16 + u] * Wo[(h * 16 + u) * 64 + c];
        g_P[i] = s;
    }
}

// ---------------- MHSA + mean over all docs (one warp per doc) ----------------
// Algebra: out = sum_h y_h @ P_h,  y_h = sum_j a[h][j] * x[j],
//          a[h][j] = mean_l softmax_j(q_l . k_j / 4)
// All paired-column math uses packed f32x2 FMA (lane owns columns c0, c0+1).
__global__ __launch_bounds__(256, 2)
void mhsa_kernel(const float* __restrict__ W_word,
                 const float* __restrict__ Wq_g, const float* __restrict__ Wk_g,
                 const int* __restrict__ qids, const int* __restrict__ rids,
                 const int* __restrict__ bids,
                 int Q, int R, int B)
{
    extern __shared__ float smem[];
    float* sWq = smem;              // 4096
    float* sWk = smem + 4096;       // 4096
    float* sx  = smem + 8192;       // 8 warps * 512
    float* sq  = sx + 8 * 512;      // 8 * 512
    float* sk  = sq + 8 * 512;      // 8 * 512
    float* sy  = sk + 8 * 512;      // 8 * 256

    int tid = threadIdx.x;
    for (int i = tid; i < 4096; i += 256) { sWq[i] = Wq_g[i]; sWk[i] = Wk_g[i]; }
    __syncthreads();

    int lane = tid & 31, warp = tid >> 5;
    float* xw = sx + warp * 512;
    float* qw = sq + warp * 512;
    float* kw = sk + warp * 512;
    float* yw = sy + warp * 256;

    int T = Q + R + B;
    int gwarp = blockIdx.x * 8 + warp;
    int nwarp = gridDim.x * 8;
    int c0 = lane * 2;
    int xrow = lane >> 2, xseg = lane & 3;
    int hh = lane >> 3, jj = lane & 7;

    for (int doc = gwarp; doc < T; doc += nwarp) {
        const int* ids; float* outp;
        if (doc < Q)          { ids = qids + doc * 8;        outp = g_hq + (size_t)doc * 64; }
        else if (doc < Q + R) { int r = doc - Q;  ids = rids + r * 8; outp = g_hr + (size_t)r * 64; }
        else                  { int b = doc - Q - R; ids = bids + b * 8; outp = g_qb + (size_t)b * 64; }

        // load x[8][64] : lane -> (row = lane/4, 16-col segment = lane%4)
        int widx = ids[xrow];
        const float4* xsrc = (const float4*)(W_word + (size_t)widx * 64 + xseg * 16);
        float4* xdst = (float4*)(xw + xrow * 64 + xseg * 16);
        xdst[0] = xsrc[0]; xdst[1] = xsrc[1]; xdst[2] = xsrc[2]; xdst[3] = xsrc[3];
        __syncwarp();

        // q,k projection: lane owns 2 output cols for all 8 rows (packed FFMA2)
        u64t accq[8], acck[8];
        #pragma unroll
        for (int l = 0; l < 8; l++) { accq[l] = 0ULL; acck[l] = 0ULL; }
        #pragma unroll 4
        for (int k = 0; k < 64; k++) {
            u64t wq2 = *(const u64t*)(sWq + k * 64 + c0);
            u64t wk2 = *(const u64t*)(sWk + k * 64 + c0);
            #pragma unroll
            for (int l = 0; l < 8; l++) {
                u64t xv = pack1(xw[l * 64 + k]);
                accq[l] = ffma2(xv, wq2, accq[l]);
                acck[l] = ffma2(xv, wk2, acck[l]);
            }
        }
        #pragma unroll
        for (int l = 0; l < 8; l++) {
            *(u64t*)(qw + l * 64 + c0) = accq[l];
            *(u64t*)(kw + l * 64 + c0) = acck[l];
        }
        __syncwarp();

        // scores for lane = (head hh, key jj), all query rows l; softmax over j (8-lane groups)
        float kj[16];
        #pragma unroll
        for (int t = 0; t < 4; t++) {
            float4 kv = *(const float4*)(kw + jj * 64 + hh * 16 + t * 4);
            kj[t*4+0] = kv.x; kj[t*4+1] = kv.y; kj[t*4+2] = kv.z; kj[t*4+3] = kv.w;
        }
        float a_acc = 0.f;
        #pragma unroll
        for (int l = 0; l < 8; l++) {
            float s = 0.f;
            #pragma unroll
            for (int t = 0; t < 4; t++) {
                float4 qv = *(const float4*)(qw + l * 64 + hh * 16 + t * 4);
                s += qv.x*kj[t*4+0] + qv.y*kj[t*4+1] + qv.z*kj[t*4+2] + qv.w*kj[t*4+3];
            }
            float e = expf(s * 0.25f);   // 1/sqrt(16)
            float tsum = e;
            tsum += __shfl_xor_sync(0xffffffffu, tsum, 1);
            tsum += __shfl_xor_sync(0xffffffffu, tsum, 2);
            tsum += __shfl_xor_sync(0xffffffffu, tsum, 4);
            a_acc += e / tsum;
        }
        a_acc *= 0.125f;                 // mean over l -> a[hh][jj]

        // y_h[64]: 8-lane head group; this lane handles cols [jj*8, jj*8+8) (packed)
        float av[8];
        int base = lane & ~7;
        #pragma unroll
        for (int m = 0; m < 8; m++) av[m] = __shfl_sync(0xffffffffu, a_acc, base + m);
        u64t y01[4];
        #pragma unroll
        for (int c = 0; c < 4; c++) y01[c] = 0ULL;
        #pragma unroll
        for (int m = 0; m < 8; m++) {
            u64t am = pack1(av[m]);
            const u64t* xr = (const u64t*)(xw + m * 64 + jj * 8);
            #pragma unroll
            for (int c = 0; c < 4; c++)
                y01[c] = ffma2(am, xr[c], y01[c]);
        }
        {
            u64t* ydst = (u64t*)(yw + hh * 64 + jj * 8);
            #pragma unroll
            for (int c = 0; c < 4; c++) ydst[c] = y01[c];
        }
        __syncwarp();

        // out = sum_h y_h @ P_h ; lane owns cols c0, c0+1 (packed)
        u64t o01 = 0ULL;
        #pragma unroll
        for (int h2 = 0; h2 < 4; h2++) {
            #pragma unroll 4
            for (int d4 = 0; d4 < 16; d4++) {
                float4 yv = *(const float4*)(yw + h2 * 64 + d4 * 4);
                const float* pb = g_P + ((h2 * 64 + d4 * 4) * 64) + c0;
                o01 = ffma2(pack1(yv.x), __ldg((const u64t*)(pb)),       o01);
                o01 = ffma2(pack1(yv.y), __ldg((const u64t*)(pb + 64)),  o01);
                o01 = ffma2(pack1(yv.z), __ldg((const u64t*)(pb + 128)), o01);
                o01 = ffma2(pack1(yv.w), __ldg((const u64t*)(pb + 192)), o01);
            }
        }
        *(u64t*)(outp + c0) = o01;
        __syncwarp();
    }
}

// ---------------- profile aggregation: ent_h += h_review, deg_p += 1 ----------------
__global__ void profile_kernel(const int* __restrict__ pdst, int R) {
    int g = blockIdx.x * blockDim.x + threadIdx.x;
    int r = g >> 4, q = g & 15;
    if (r >= R) return;
    int d = pdst[r];
    float4 v = *(const float4*)(g_hr + (size_t)r * 64 + q * 4);
    red_add_v4(g_enth + (size_t)d * 64 + q * 4, v);
    if (q == 0) atomicAdd(g_degp + d, 1.0f);
}

// ---------------- interaction degree ----------------
__global__ void degi_kernel(const int* __restrict__ ps, const int* __restrict__ pd, int E) {
    int g = blockIdx.x * blockDim.x + threadIdx.x;
    if (g >= E) return;
    atomicAdd(g_degi + ps[g], 1.0f);
    atomicAdd(g_degi + pd[g], 1.0f);
}

// ---------------- build e_0, q_e0, inv_sqrt ----------------
__global__ void build_kernel(const float* __restrict__ W_query,
                             const float* __restrict__ W_entity, int Q, int N) {
    int g = blockIdx.x * blockDim.x + threadIdx.x;
    int n = g >> 5, lane = g & 31;
    if (n >= N) return;
    int c = lane * 4;
    if (lane == 0) g_invs[n] = 1.0f / sqrtf(fmaxf(g_degi[n], 1.0f));
    float4 v;
    if (c < 64) {
        v = *(const float4*)(W_entity + (size_t)n * 64 + c);
    } else {
        float invdp = 1.0f / fmaxf(g_degp[n], 1.0f);
        float4 hv = *(const float4*)(g_enth + (size_t)n * 64 + (c - 64));
        v = make_float4(hv.x * invdp, hv.y * invdp, hv.z * invdp, hv.w * invdp);
    }
    *(float4*)(g_ek + (size_t)n * 128 + c) = v;
    if (n < Q) {
        float4 u;
        if (c < 64) u = *(const float4*)(W_query + (size_t)n * 64 + c);
        else        u = *(const float4*)(g_hq + (size_t)n * 64 + (c - 64));
        *(float4*)(g_qe0 + (size_t)n * 128 + c) = u;
    }
}

// ---------------- edge conv (both directions fused), one warp per edge ----------------
__global__ void edge_kernel(const int* __restrict__ ps, const int* __restrict__ pd,
                            const int* __restrict__ pq, int E) {
    long long g = (long long)blockIdx.x * blockDim.x + threadIdx.x;
    int e = (int)(g >> 5);
    int lane = (int)(g & 31);
    if (e >= E) return;
    int src = ps[e], dst = pd[e], qid = pq[e];
    float iss = g_invs[src];
    float isd = g_invs[dst];
    int c = lane * 4;
    float4 es = *(const float4*)(g_ek + (size_t)src * 128 + c);
    float4 qv = *(const float4*)(g_qe0 + (size_t)qid * 128 + c);
    float4 m = make_float4(es.x + qv.x * iss, es.y + qv.y * iss,
                           es.z + qv.z * iss, es.w + qv.w * iss);
    red_add_v4(g_agg + (size_t)dst * 128 + c, m);
    float4 ed = *(const float4*)(g_ek + (size_t)dst * 128 + c);
    float4 m2 = make_float4(ed.x * isd, ed.y * isd, ed.z * isd, ed.w * isd);
    red_add_v4(g_agg + (size_t)src * 128 + c, m2);
}

// ---------------- output: gather e = (e0 + agg*inv)/2 at users/items/negs ----------------
__global__ void output_kernel(const int* __restrict__ users, const int* __restrict__ items,
                              const int* __restrict__ negs, int B, float* __restrict__ out) {
    int g = blockIdx.x * blockDim.x + threadIdx.x;
    int idx = g >> 5, lane = g & 31;
    if (idx >= 3 * B) return;
    int part = idx / B, b = idx % B;
    int r = (part == 0) ? users[b] : ((part == 1) ? items[b] : negs[b]);
    int c = lane * 4;
    float inv = g_invs[r];
    float4 ev = *(const float4*)(g_ek + (size_t)r * 128 + c);
    float4 av = *(const float4*)(g_agg + (size_t)r * 128 + c);
    float4 v = make_float4((ev.x + av.x * inv) * 0.5f, (ev.y + av.y * inv) * 0.5f,
                           (ev.z + av.z * inv) * 0.5f, (ev.w + av.w * inv) * 0.5f);
    if (part == 0 && c >= 64) {
        float4 qb = *(const float4*)(g_qb + (size_t)b * 64 + (c - 64));
        v.x += qb.x; v.y += qb.y; v.z += qb.z; v.w += qb.w;
    }
    *(float4*)(out + (size_t)idx * 128 + c) = v;
}

// ---------------- launch ----------------
extern "C" void kernel_launch(void* const* d_in, const int* in_sizes, int n_in,
                              void* d_out, int out_size) {
    const float* W_word   = (const float*)d_in[0];
    const float* W_query  = (const float*)d_in[1];
    const float* W_entity = (const float*)d_in[2];
    const float* Wq       = (const float*)d_in[3];
    const float* Wk       = (const float*)d_in[4];
    const float* Wv       = (const float*)d_in[5];
    const float* Wo       = (const float*)d_in[6];
    const int* qids   = (const int*)d_in[7];
    const int* rids   = (const int*)d_in[8];
    const int* pdst   = (const int*)d_in[9];
    const int* p_src  = (const int*)d_in[10];
    const int* p_dst  = (const int*)d_in[11];
    const int* p_qid  = (const int*)d_in[12];
    const int* users  = (const int*)d_in[13];
    const int* items  = (const int*)d_in[14];
    const int* negs   = (const int*)d_in[15];
    const int* qwords = (const int*)d_in[16];

    int Q = in_sizes[1] / 64;
    int N = in_sizes[2] / 64;
    int R = in_sizes[9];
    int E = in_sizes[10];
    int B = in_sizes[13];

    zero_kernel<<<4096, 256>>>(N);
    precompute_P<<<1, 256>>>(Wv, Wo);

    size_t smem_bytes = (size_t)(8192 + 8 * 512 * 3 + 8 * 256) * sizeof(float); // 90112 B
    cudaFuncSetAttribute(mhsa_kernel, cudaFuncAttributeMaxDynamicSharedMemorySize,
                         (int)smem_bytes);
    mhsa_kernel<<<1184, 256, smem_bytes>>>(W_word, Wq, Wk, qids, rids, qwords, Q, R, B);

    profile_kernel<<<(R * 16 + 255) / 256, 256>>>(pdst, R);
    degi_kernel<<<(E + 255) / 256, 256>>>(p_src, p_dst, E);
    build_kernel<<<(N * 32 + 255) / 256, 256>>>(W_query, W_entity, Q, N);

    long long ethreads = (long long)E * 32;
    edge_kernel<<<(int)((ethreads + 255) / 256), 256>>>(p_src, p_dst, p_qid, E);

    output_kernel<<<(3 * B * 32 + 255) / 256, 256>>>(users, items, negs, B, (float*)d_out);
}

// round 5
// speedup vs baseline: 1.7063x; 1.5605x over previous
#include <cuda_runtime.h>
#include <math.h>
#include <stdint.h>

// Problem dimensions (fixed dataset; runtime values still read from in_sizes)
#define WORD_N   50000
#define QUERY_N  50000
#define ENT_N    100000
#define REV_N    100000
#define BATCH_N  1024
#define DWDIM    64
#define DDIM     128

typedef unsigned long long u64t;

// ---------------- scratch (static __device__, no allocation) ----------------
__device__ __align__(16) float g_hq[QUERY_N * DWDIM];
__device__ __align__(16) float g_hr[REV_N * DWDIM];
__device__ __align__(16) float g_qb[BATCH_N * DWDIM];
__device__ __align__(16) float g_enth[ENT_N * DWDIM];
__device__ __align__(16) float g_degp[ENT_N];
__device__ __align__(16) float g_degi[ENT_N];
__device__ __align__(16) float g_invs[ENT_N];
__device__ __align__(16) float g_ek[ENT_N * DDIM];
__device__ __align__(16) float g_qe0[QUERY_N * DDIM];
__device__ __align__(16) float g_agg[ENT_N * DDIM];
__device__ __align__(16) float g_P[4 * 64 * 64];        // P_h = Wv[:,h16] @ Wo[h16,:]
__device__ __align__(16) float g_QKW[WORD_N * 128];     // per word: [q(64) | k(64)]
__device__ __align__(16) float g_Z[WORD_N * 256];       // per word: [h0(64)|h1|h2|h3] = x_w @ P_h

// ---------------- helpers ----------------
__device__ __forceinline__ u64t pack1(float x) {
    u64t r; asm("mov.b64 %0, {%1,%1};" : "=l"(r) : "f"(x)); return r;
}
__device__ __forceinline__ u64t ffma2(u64t a, u64t b, u64t c) {
    u64t d; asm("fma.rn.f32x2 %0, %1, %2, %3;" : "=l"(d) : "l"(a), "l"(b), "l"(c));
    return d;
}
__device__ __forceinline__ void red_add_v4(float* p, float4 v) {
    asm volatile("red.global.add.v4.f32 [%0], {%1,%2,%3,%4};"
                 :: "l"(p), "f"(v.x), "f"(v.y), "f"(v.z), "f"(v.w) : "memory");
}

// ---------------- zero scratch ----------------
__global__ void zero_kernel(int N) {
    int g = blockIdx.x * blockDim.x + threadIdx.x;
    int stride = gridDim.x * blockDim.x;
    float4 z = make_float4(0.f, 0.f, 0.f, 0.f);
    int n_agg4 = N * 32;
    for (int i = g; i < n_agg4; i += stride) ((float4*)g_agg)[i] = z;
    int n_eh4 = N * 16;
    for (int i = g; i < n_eh4; i += stride) ((float4*)g_enth)[i] = z;
    int n4 = N / 4;
    for (int i = g; i < n4; i += stride) { ((float4*)g_degp)[i] = z; ((float4*)g_degi)[i] = z; }
}

// ---------------- precompute P_h = Wv[:, h*16:(h+1)*16] @ Wo[h*16:(h+1)*16, :] ----------------
__global__ void precompute_P(const float* __restrict__ Wv, const float* __restrict__ Wo) {
    int t = blockIdx.x * blockDim.x + threadIdx.x;
    if (t >= 4 * 64 * 64) return;
    int h = t >> 12, d = (t >> 6) & 63, c = t & 63;
    float s = 0.f;
    #pragma unroll
    for (int u = 0; u < 16; u++)
        s += Wv[d * 64 + h * 16 + u] * Wo[(h * 16 + u) * 64 + c];
    g_P[t] = s;
}

// ---------------- precompute QK[w] = x_w @ [Wq | Wk]  (one warp per word) ----------------
__global__ __launch_bounds__(256) void precompute_QK(
    const float* __restrict__ W_word, const float* __restrict__ Wq,
    const float* __restrict__ Wk, int NW)
{
    __shared__ float sW[64 * 128];   // [k][n]: n<64 -> Wq col n, else Wk col n-64
    int tid = threadIdx.x;
    for (int i = tid; i < 64 * 128; i += 256) {
        int k = i >> 7, n = i & 127;
        sW[i] = (n < 64) ? Wq[k * 64 + n] : Wk[k * 64 + (n - 64)];
    }
    __syncthreads();
    int lane = tid & 31, warp = tid >> 5;
    for (int w = blockIdx.x * 8 + warp; w < NW; w += gridDim.x * 8) {
        float2 xr = *(const float2*)(W_word + (size_t)w * 64 + lane * 2);
        u64t a0 = 0, a1 = 0;
        #pragma unroll 8
        for (int k = 0; k < 64; k++) {
            float xs = __shfl_sync(0xffffffffu, (k & 1) ? xr.y : xr.x, k >> 1);
            u64t xv = pack1(xs);
            a0 = ffma2(xv, *(const u64t*)(sW + k * 128 + lane * 2), a0);
            a1 = ffma2(xv, *(const u64t*)(sW + k * 128 + 64 + lane * 2), a1);
        }
        *(u64t*)(g_QKW + (size_t)w * 128 + lane * 2) = a0;
        *(u64t*)(g_QKW + (size_t)w * 128 + 64 + lane * 2) = a1;
    }
}

// ---------------- precompute Z[w, h*64+c] = sum_d x_w[d] * P[h][d][c] ----------------
__global__ __launch_bounds__(256) void precompute_Z(const float* __restrict__ W_word, int NW) {
    extern __shared__ float sP[];    // 16384 floats = 64 KB, layout [h][d][c]
    int tid = threadIdx.x;
    for (int i = tid; i < 16384; i += 256) sP[i] = g_P[i];
    __syncthreads();
    int lane = tid & 31, warp = tid >> 5;
    for (int w = blockIdx.x * 8 + warp; w < NW; w += gridDim.x * 8) {
        float2 xr = *(const float2*)(W_word + (size_t)w * 64 + lane * 2);
        u64t acc[4] = {0, 0, 0, 0};
        #pragma unroll 8
        for (int d = 0; d < 64; d++) {
            float xs = __shfl_sync(0xffffffffu, (d & 1) ? xr.y : xr.x, d >> 1);
            u64t xv = pack1(xs);
            #pragma unroll
            for (int h = 0; h < 4; h++)
                acc[h] = ffma2(xv, *(const u64t*)(sP + h * 4096 + d * 64 + lane * 2), acc[h]);
        }
        #pragma unroll
        for (int h = 0; h < 4; h++)
            *(u64t*)(g_Z + (size_t)w * 256 + h * 64 + lane * 2) = acc[h];
    }
}

// ---------------- attention: scores + softmax + Z-combine (one warp per doc) ----------------
__global__ __launch_bounds__(256)
void attn_kernel(const int* __restrict__ qids, const int* __restrict__ rids,
                 const int* __restrict__ bids, int Q, int R, int B)
{
    int tid = threadIdx.x, lane = tid & 31, warp = tid >> 5;
    int T = Q + R + B;
    int hh = lane >> 3, jj = lane & 7;

    for (int doc = blockIdx.x * 8 + warp; doc < T; doc += gridDim.x * 8) {
        const int* ids; float* outp;
        if (doc < Q)          { ids = qids + (size_t)doc * 8;       outp = g_hq + (size_t)doc * 64; }
        else if (doc < Q + R) { int r = doc - Q; ids = rids + (size_t)r * 8; outp = g_hr + (size_t)r * 64; }
        else                  { int b = doc - Q - R; ids = bids + (size_t)b * 8; outp = g_qb + (size_t)b * 64; }

        int myid = ids[jj];                      // lane (hh,jj) caches ids[jj]

        // k vector for (head hh, key jj): QK[myid][64 + hh*16 .. +16]
        const float4* kp = (const float4*)(g_QKW + (size_t)myid * 128 + 64 + hh * 16);
        float4 k0 = __ldg(kp), k1 = __ldg(kp + 1), k2 = __ldg(kp + 2), k3 = __ldg(kp + 3);

        float a_acc = 0.f;
        #pragma unroll
        for (int l = 0; l < 8; l++) {
            int idl = __shfl_sync(0xffffffffu, myid, l);    // lane l holds ids[l]
            const float4* qp = (const float4*)(g_QKW + (size_t)idl * 128 + hh * 16);
            float4 q0 = __ldg(qp), q1 = __ldg(qp + 1), q2 = __ldg(qp + 2), q3 = __ldg(qp + 3);
            float s = q0.x*k0.x + q0.y*k0.y + q0.z*k0.z + q0.w*k0.w
                    + q1.x*k1.x + q1.y*k1.y + q1.z*k1.z + q1.w*k1.w
                    + q2.x*k2.x + q2.y*k2.y + q2.z*k2.z + q2.w*k2.w
                    + q3.x*k3.x + q3.y*k3.y + q3.z*k3.z + q3.w*k3.w;
            float e = __expf(s * 0.25f);         // 1/sqrt(16)
            float t = e;
            t += __shfl_xor_sync(0xffffffffu, t, 1);
            t += __shfl_xor_sync(0xffffffffu, t, 2);
            t += __shfl_xor_sync(0xffffffffu, t, 4);
            a_acc += e * __frcp_rn(t);
        }
        a_acc *= 0.125f;                         // mean over l -> a[hh][jj]

        // out[c0,c0+1] = sum_{j,h} a[h][j] * Z[ids[j]][h*64 + c0..c0+1]
        int c0 = lane * 2;
        u64t o = 0;
        #pragma unroll
        for (int j = 0; j < 8; j++) {
            int idz = __shfl_sync(0xffffffffu, myid, j);
            const float* zr = g_Z + (size_t)idz * 256 + c0;
            #pragma unroll
            for (int h = 0; h < 4; h++) {
                float av = __shfl_sync(0xffffffffu, a_acc, h * 8 + j);
                o = ffma2(pack1(av), __ldg((const u64t*)(zr + h * 64)), o);
            }
        }
        *(u64t*)(outp + c0) = o;
        __syncwarp();
    }
}

// ---------------- profile aggregation: ent_h += h_review, deg_p += 1 ----------------
__global__ void profile_kernel(const int* __restrict__ pdst, int R) {
    int g = blockIdx.x * blockDim.x + threadIdx.x;
    int r = g >> 4, q = g & 15;
    if (r >= R) return;
    int d = pdst[r];
    float4 v = *(const float4*)(g_hr + (size_t)r * 64 + q * 4);
    red_add_v4(g_enth + (size_t)d * 64 + q * 4, v);
    if (q == 0) atomicAdd(g_degp + d, 1.0f);
}

// ---------------- interaction degree ----------------
__global__ void degi_kernel(const int* __restrict__ ps, const int* __restrict__ pd, int E) {
    int g = blockIdx.x * blockDim.x + threadIdx.x;
    if (g >= E) return;
    atomicAdd(g_degi + ps[g], 1.0f);
    atomicAdd(g_degi + pd[g], 1.0f);
}

// ---------------- build e_0, q_e0, inv_sqrt ----------------
__global__ void build_kernel(const float* __restrict__ W_query,
                             const float* __restrict__ W_entity, int Q, int N) {
    int g = blockIdx.x * blockDim.x + threadIdx.x;
    int n = g >> 5, lane = g & 31;
    if (n >= N) return;
    int c = lane * 4;
    if (lane == 0) g_invs[n] = 1.0f / sqrtf(fmaxf(g_degi[n], 1.0f));
    float4 v;
    if (c < 64) {
        v = *(const float4*)(W_entity + (size_t)n * 64 + c);
    } else {
        float invdp = 1.0f / fmaxf(g_degp[n], 1.0f);
        float4 hv = *(const float4*)(g_enth + (size_t)n * 64 + (c - 64));
        v = make_float4(hv.x * invdp, hv.y * invdp, hv.z * invdp, hv.w * invdp);
    }
    *(float4*)(g_ek + (size_t)n * 128 + c) = v;
    if (n < Q) {
        float4 u;
        if (c < 64) u = *(const float4*)(W_query + (size_t)n * 64 + c);
        else        u = *(const float4*)(g_hq + (size_t)n * 64 + (c - 64));
        *(float4*)(g_qe0 + (size_t)n * 128 + c) = u;
    }
}

// ---------------- edge conv (both directions fused), one warp per edge ----------------
__global__ void edge_kernel(const int* __restrict__ ps, const int* __restrict__ pd,
                            const int* __restrict__ pq, int E) {
    long long g = (long long)blockIdx.x * blockDim.x + threadIdx.x;
    int e = (int)(g >> 5);
    int lane = (int)(g & 31);
    if (e >= E) return;
    int src = ps[e], dst = pd[e], qid = pq[e];
    float iss = g_invs[src];
    float isd = g_invs[dst];
    int c = lane * 4;
    float4 es = *(const float4*)(g_ek + (size_t)src * 128 + c);
    float4 qv = *(const float4*)(g_qe0 + (size_t)qid * 128 + c);
    float4 m = make_float4(es.x + qv.x * iss, es.y + qv.y * iss,
                           es.z + qv.z * iss, es.w + qv.w * iss);
    red_add_v4(g_agg + (size_t)dst * 128 + c, m);
    float4 ed = *(const float4*)(g_ek + (size_t)dst * 128 + c);
    float4 m2 = make_float4(ed.x * isd, ed.y * isd, ed.z * isd, ed.w * isd);
    red_add_v4(g_agg + (size_t)src * 128 + c, m2);
}

// ---------------- output: gather e = (e0 + agg*inv)/2 at users/items/negs ----------------
__global__ void output_kernel(const int* __restrict__ users, const int* __restrict__ items,
                              const int* __restrict__ negs, int B, float* __restrict__ out) {
    int g = blockIdx.x * blockDim.x + threadIdx.x;
    int idx = g >> 5, lane = g & 31;
    if (idx >= 3 * B) return;
    int part = idx / B, b = idx % B;
    int r = (part == 0) ? users[b] : ((part == 1) ? items[b] : negs[b]);
    int c = lane * 4;
    float inv = g_invs[r];
    float4 ev = *(const float4*)(g_ek + (size_t)r * 128 + c);
    float4 av = *(const float4*)(g_agg + (size_t)r * 128 + c);
    float4 v = make_float4((ev.x + av.x * inv) * 0.5f, (ev.y + av.y * inv) * 0.5f,
                           (ev.z + av.z * inv) * 0.5f, (ev.w + av.w * inv) * 0.5f);
    if (part == 0 && c >= 64) {
        float4 qb = *(const float4*)(g_qb + (size_t)b * 64 + (c - 64));
        v.x += qb.x; v.y += qb.y; v.z += qb.z; v.w += qb.w;
    }
    *(float4*)(out + (size_t)idx * 128 + c) = v;
}

// ---------------- launch ----------------
extern "C" void kernel_launch(void* const* d_in, const int* in_sizes, int n_in,
                              void* d_out, int out_size) {
    const float* W_word   = (const float*)d_in[0];
    const float* W_query  = (const float*)d_in[1];
    const float* W_entity = (const float*)d_in[2];
    const float* Wq       = (const float*)d_in[3];
    const float* Wk       = (const float*)d_in[4];
    const float* Wv       = (const float*)d_in[5];
    const float* Wo       = (const float*)d_in[6];
    const int* qids   = (const int*)d_in[7];
    const int* rids   = (const int*)d_in[8];
    const int* pdst   = (const int*)d_in[9];
    const int* p_src  = (const int*)d_in[10];
    const int* p_dst  = (const int*)d_in[11];
    const int* p_qid  = (const int*)d_in[12];
    const int* users  = (const int*)d_in[13];
    const int* items  = (const int*)d_in[14];
    const int* negs   = (const int*)d_in[15];
    const int* qwords = (const int*)d_in[16];

    int NW = in_sizes[0] / 64;
    int Q = in_sizes[1] / 64;
    int N = in_sizes[2] / 64;
    int R = in_sizes[9];
    int E = in_sizes[10];
    int B = in_sizes[13];

    zero_kernel<<<4096, 256>>>(N);
    precompute_P<<<64, 256>>>(Wv, Wo);
    precompute_QK<<<592, 256>>>(W_word, Wq, Wk, NW);

    cudaFuncSetAttribute(precompute_Z, cudaFuncAttributeMaxDynamicSharedMemorySize, 65536);
    precompute_Z<<<592, 256, 65536>>>(W_word, NW);

    attn_kernel<<<1184, 256>>>(qids, rids, qwords, Q, R, B);

    profile_kernel<<<(R * 16 + 255) / 256, 256>>>(pdst, R);
    degi_kernel<<<(E + 255) / 256, 256>>>(p_src, p_dst, E);
    build_kernel<<<(N * 32 + 255) / 256, 256>>>(W_query, W_entity, Q, N);

    long long ethreads = (long long)E * 32;
    edge_kernel<<<(int)((ethreads + 255) / 256), 256>>>(p_src, p_dst, p_qid, E);

    output_kernel<<<(3 * B * 32 + 255) / 256, 256>>>(users, items, negs, B, (float*)d_out);
}

// round 7
// speedup vs baseline: 1.8657x; 1.0934x over previous
#include <cuda_runtime.h>
#include <math.h>
#include <stdint.h>

// Problem dimensions (fixed dataset; runtime values still read from in_sizes)
#define WORD_N   50000
#define QUERY_N  50000
#define ENT_N    100000
#define REV_N    100000
#define BATCH_N  1024
#define DWDIM    64
#define DDIM     128

typedef unsigned long long u64t;

// ---------------- scratch (static __device__, no allocation) ----------------
__device__ __align__(16) float g_hq[QUERY_N * DWDIM];
__device__ __align__(16) float g_hr[REV_N * DWDIM];
__device__ __align__(16) float g_qb[BATCH_N * DWDIM];
__device__ __align__(16) float g_enth[ENT_N * DWDIM];
__device__ __align__(16) float g_degp[ENT_N];
__device__ __align__(16) float g_degi[ENT_N];
__device__ __align__(16) float g_invs[ENT_N];
__device__ __align__(16) float g_ek[ENT_N * DDIM];
__device__ __align__(16) float g_qe0[QUERY_N * DDIM];
__device__ __align__(16) float g_agg[ENT_N * DDIM];
__device__ __align__(16) float g_P[4 * 64 * 64];        // P_h = Wv[:,h16] @ Wo[h16,:]
__device__ __align__(16) float g_QKW[WORD_N * 128];     // per word: [q(64) | k(64)]
__device__ __align__(16) float g_Z[WORD_N * 256];       // per word: [h0|h1|h2|h3] = x_w @ P_h

// ---------------- helpers ----------------
__device__ __forceinline__ u64t pack1(float x) {
    u64t r; asm("mov.b64 %0, {%1,%1};" : "=l"(r) : "f"(x)); return r;
}
__device__ __forceinline__ u64t ffma2(u64t a, u64t b, u64t c) {
    u64t d; asm("fma.rn.f32x2 %0, %1, %2, %3;" : "=l"(d) : "l"(a), "l"(b), "l"(c));
    return d;
}
__device__ __forceinline__ void red_add_v4(float* p, float4 v) {
    asm volatile("red.global.add.v4.f32 [%0], {%1,%2,%3,%4};"
                 :: "l"(p), "f"(v.x), "f"(v.y), "f"(v.z), "f"(v.w) : "memory");
}

// ---------------- zero scratch ----------------
__global__ void zero_kernel(int N) {
    int g = blockIdx.x * blockDim.x + threadIdx.x;
    int stride = gridDim.x * blockDim.x;
    float4 z = make_float4(0.f, 0.f, 0.f, 0.f);
    int n_agg4 = N * 32;
    for (int i = g; i < n_agg4; i += stride) ((float4*)g_agg)[i] = z;
    int n_eh4 = N * 16;
    for (int i = g; i < n_eh4; i += stride) ((float4*)g_enth)[i] = z;
    int n4 = N / 4;
    for (int i = g; i < n4; i += stride) { ((float4*)g_degp)[i] = z; ((float4*)g_degi)[i] = z; }
}

// ---------------- precompute P_h = Wv[:, h*16:(h+1)*16] @ Wo[h*16:(h+1)*16, :] ----------------
__global__ void precompute_P(const float* __restrict__ Wv, const float* __restrict__ Wo) {
    int t = blockIdx.x * blockDim.x + threadIdx.x;
    if (t >= 4 * 64 * 64) return;
    int h = t >> 12, d = (t >> 6) & 63, c = t & 63;
    float s = 0.f;
    #pragma unroll
    for (int u = 0; u < 16; u++)
        s += Wv[d * 64 + h * 16 + u] * Wo[(h * 16 + u) * 64 + c];
    g_P[t] = s;
}

// ---------------- fused Z + QK precompute:  [Z | Q | K](w) = x_w @ [P | Wq | Wk] ----------------
// B (64x384) in smem once per block; x pre-packed {x,x}. Thread owns col-pair x 8 words.
__global__ __launch_bounds__(384) void fuse_zqk(
    const float* __restrict__ W_word, const float* __restrict__ Wq,
    const float* __restrict__ Wk, int NW)
{
    extern __shared__ char sm[];
    float* sB = (float*)sm;                   // 64*384 floats = 98304 B
    u64t* sx2 = (u64t*)(sm + 98304);          // 64*16 u64 = 8192 B
    int t = threadIdx.x;

    for (int i = t; i < 24576; i += 384) {
        int d = i / 384, c = i % 384;
        float v;
        if (c < 256)      v = g_P[((c >> 6) << 12) + d * 64 + (c & 63)];
        else if (c < 320) v = Wq[d * 64 + (c - 256)];
        else              v = Wk[d * 64 + (c - 320)];
        sB[d * 384 + c] = v;
    }

    int wgroup = t / 192;            // 0 or 1 -> words 0..7 / 8..15 of tile
    int cpair = t % 192;
    int c0 = cpair * 2;
    int ntiles = (NW + 15) / 16;

    for (int tile = blockIdx.x; tile < ntiles; tile += gridDim.x) {
        __syncthreads();
        for (int i = t; i < 1024; i += 384) {
            int wi = i >> 6, d = i & 63;
            int w = tile * 16 + wi;
            float v = W_word[(size_t)(w < NW ? w : 0) * 64 + d];
            sx2[d * 16 + wi] = pack1(v);
        }
        __syncthreads();

        u64t acc0 = 0ULL, acc1 = 0ULL, acc2 = 0ULL, acc3 = 0ULL;
        u64t acc4 = 0ULL, acc5 = 0ULL, acc6 = 0ULL, acc7 = 0ULL;
        #pragma unroll 4
        for (int d = 0; d < 64; d++) {
            u64t b2 = *(const u64t*)(sB + d * 384 + c0);
            const u64t* xr = sx2 + d * 16 + wgroup * 8;
            acc0 = ffma2(xr[0], b2, acc0);
            acc1 = ffma2(xr[1], b2, acc1);
            acc2 = ffma2(xr[2], b2, acc2);
            acc3 = ffma2(xr[3], b2, acc3);
            acc4 = ffma2(xr[4], b2, acc4);
            acc5 = ffma2(xr[5], b2, acc5);
            acc6 = ffma2(xr[6], b2, acc6);
            acc7 = ffma2(xr[7], b2, acc7);
        }
        int wbase = tile * 16 + wgroup * 8;
        size_t stride_out;
        float* outb;
        if (c0 < 256)      { outb = g_Z + (size_t)wbase * 256 + c0;              stride_out = 256; }
        else if (c0 < 320) { outb = g_QKW + (size_t)wbase * 128 + (c0 - 256);    stride_out = 128; }
        else               { outb = g_QKW + (size_t)wbase * 128 + 64 + (c0 - 320); stride_out = 128; }
        int nvalid = NW - wbase;     // >= 8 except final tile
        if (nvalid >= 8) {
            *(u64t*)(outb)                  = acc0;
            *(u64t*)(outb + stride_out)     = acc1;
            *(u64t*)(outb + stride_out * 2) = acc2;
            *(u64t*)(outb + stride_out * 3) = acc3;
            *(u64t*)(outb + stride_out * 4) = acc4;
            *(u64t*)(outb + stride_out * 5) = acc5;
            *(u64t*)(outb + stride_out * 6) = acc6;
            *(u64t*)(outb + stride_out * 7) = acc7;
        } else if (nvalid > 0) {
            if (nvalid > 0) *(u64t*)(outb)                  = acc0;
            if (nvalid > 1) *(u64t*)(outb + stride_out)     = acc1;
            if (nvalid > 2) *(u64t*)(outb + stride_out * 2) = acc2;
            if (nvalid > 3) *(u64t*)(outb + stride_out * 3) = acc3;
            if (nvalid > 4) *(u64t*)(outb + stride_out * 4) = acc4;
            if (nvalid > 5) *(u64t*)(outb + stride_out * 5) = acc5;
            if (nvalid > 6) *(u64t*)(outb + stride_out * 6) = acc6;
        }
    }
}

// ---------------- attention: scores + softmax + Z-combine (one warp per doc) ----------------
__global__ __launch_bounds__(256)
void attn_kernel(const int* __restrict__ qids, const int* __restrict__ rids,
                 const int* __restrict__ bids, int Q, int R, int B)
{
    int tid = threadIdx.x, lane = tid & 31, warp = tid >> 5;
    int T = Q + R + B;
    int hh = lane >> 3, jj = lane & 7;

    for (int doc = blockIdx.x * 8 + warp; doc < T; doc += gridDim.x * 8) {
        const int* ids; float* outp;
        if (doc < Q)          { ids = qids + (size_t)doc * 8;       outp = g_hq + (size_t)doc * 64; }
        else if (doc < Q + R) { int r = doc - Q; ids = rids + (size_t)r * 8; outp = g_hr + (size_t)r * 64; }
        else                  { int b = doc - Q - R; ids = bids + (size_t)b * 8; outp = g_qb + (size_t)b * 64; }

        int myid = ids[jj];

        const float4* kp = (const float4*)(g_QKW + (size_t)myid * 128 + 64 + hh * 16);
        float4 k0 = __ldg(kp), k1 = __ldg(kp + 1), k2 = __ldg(kp + 2), k3 = __ldg(kp + 3);

        float a_acc = 0.f;
        #pragma unroll
        for (int l = 0; l < 8; l++) {
            int idl = __shfl_sync(0xffffffffu, myid, l);
            const float4* qp = (const float4*)(g_QKW + (size_t)idl * 128 + hh * 16);
            float4 q0 = __ldg(qp), q1 = __ldg(qp + 1), q2 = __ldg(qp + 2), q3 = __ldg(qp + 3);
            float s = q0.x*k0.x + q0.y*k0.y + q0.z*k0.z + q0.w*k0.w
                    + q1.x*k1.x + q1.y*k1.y + q1.z*k1.z + q1.w*k1.w
                    + q2.x*k2.x + q2.y*k2.y + q2.z*k2.z + q2.w*k2.w
                    + q3.x*k3.x + q3.y*k3.y + q3.z*k3.z + q3.w*k3.w;
            float e = __expf(s * 0.25f);
            float t = e;
            t += __shfl_xor_sync(0xffffffffu, t, 1);
            t += __shfl_xor_sync(0xffffffffu, t, 2);
            t += __shfl_xor_sync(0xffffffffu, t, 4);
            a_acc += e * __frcp_rn(t);
        }
        a_acc *= 0.125f;

        int c0 = lane * 2;
        u64t o = 0;
        #pragma unroll
        for (int j = 0; j < 8; j++) {
            int idz = __shfl_sync(0xffffffffu, myid, j);
            const float* zr = g_Z + (size_t)idz * 256 + c0;
            #pragma unroll
            for (int h = 0; h < 4; h++) {
                float av = __shfl_sync(0xffffffffu, a_acc, h * 8 + j);
                o = ffma2(pack1(av), __ldg((const u64t*)(zr + h * 64)), o);
            }
        }
        *(u64t*)(outp + c0) = o;
        __syncwarp();
    }
}

// ---------------- profile aggregation: ent_h += h_review, deg_p += 1 ----------------
__global__ void profile_kernel(const int* __restrict__ pdst, int R) {
    int g = blockIdx.x * blockDim.x + threadIdx.x;
    int r = g >> 4, q = g & 15;
    if (r >= R) return;
    int d = pdst[r];
    float4 v = *(const float4*)(g_hr + (size_t)r * 64 + q * 4);
    red_add_v4(g_enth + (size_t)d * 64 + q * 4, v);
    if (q == 0) atomicAdd(g_degp + d, 1.0f);
}

// ---------------- interaction degree ----------------
__global__ void degi_kernel(const int* __restrict__ ps, const int* __restrict__ pd, int E) {
    int g = blockIdx.x * blockDim.x + threadIdx.x;
    if (g >= E) return;
    atomicAdd(g_degi + ps[g], 1.0f);
    atomicAdd(g_degi + pd[g], 1.0f);
}

// ---------------- build e_0, q_e0, inv_sqrt ----------------
__global__ void build_kernel(const float* __restrict__ W_query,
                             const float* __restrict__ W_entity, int Q, int N) {
    int g = blockIdx.x * blockDim.x + threadIdx.x;
    int n = g >> 5, lane = g & 31;
    if (n >= N) return;
    int c = lane * 4;
    if (lane == 0) g_invs[n] = 1.0f / sqrtf(fmaxf(g_degi[n], 1.0f));
    float4 v;
    if (c < 64) {
        v = *(const float4*)(W_entity + (size_t)n * 64 + c);
    } else {
        float invdp = 1.0f / fmaxf(g_degp[n], 1.0f);
        float4 hv = *(const float4*)(g_enth + (size_t)n * 64 + (c - 64));
        v = make_float4(hv.x * invdp, hv.y * invdp, hv.z * invdp, hv.w * invdp);
    }
    *(float4*)(g_ek + (size_t)n * 128 + c) = v;
    if (n < Q) {
        float4 u;
        if (c < 64) u = *(const float4*)(W_query + (size_t)n * 64 + c);
        else        u = *(const float4*)(g_hq + (size_t)n * 64 + (c - 64));
        *(float4*)(g_qe0 + (size_t)n * 128 + c) = u;
    }
}

// ---------------- edge conv (both directions fused), one warp per edge ----------------
__global__ void edge_kernel(const int* __restrict__ ps, const int* __restrict__ pd,
                            const int* __restrict__ pq, int E) {
    long long g = (long long)blockIdx.x * blockDim.x + threadIdx.x;
    int e = (int)(g >> 5);
    int lane = (int)(g & 31);
    if (e >= E) return;
    int src = ps[e], dst = pd[e], qid = pq[e];
    float iss = g_invs[src];
    float isd = g_invs[dst];
    int c = lane * 4;
    float4 es = *(const float4*)(g_ek + (size_t)src * 128 + c);
    float4 qv = *(const float4*)(g_qe0 + (size_t)qid * 128 + c);
    float4 m = make_float4(es.x + qv.x * iss, es.y + qv.y * iss,
                           es.z + qv.z * iss, es.w + qv.w * iss);
    red_add_v4(g_agg + (size_t)dst * 128 + c, m);
    float4 ed = *(const float4*)(g_ek + (size_t)dst * 128 + c);
    float4 m2 = make_float4(ed.x * isd, ed.y * isd, ed.z * isd, ed.w * isd);
    red_add_v4(g_agg + (size_t)src * 128 + c, m2);
}

// ---------------- output: gather e = (e0 + agg*inv)/2 at users/items/negs ----------------
__global__ void output_kernel(const int* __restrict__ users, const int* __restrict__ items,
                              const int* __restrict__ negs, int B, float* __restrict__ out) {
    int g = blockIdx.x * blockDim.x + threadIdx.x;
    int idx = g >> 5, lane = g & 31;
    if (idx >= 3 * B) return;
    int part = idx / B, b = idx % B;
    int r = (part == 0) ? users[b] : ((part == 1) ? items[b] : negs[b]);
    int c = lane * 4;
    float inv = g_invs[r];
    float4 ev = *(const float4*)(g_ek + (size_t)r * 128 + c);
    float4 av = *(const float4*)(g_agg + (size_t)r * 128 + c);
    float4 v = make_float4((ev.x + av.x * inv) * 0.5f, (ev.y + av.y * inv) * 0.5f,
                           (ev.z + av.z * inv) * 0.5f, (ev.w + av.w * inv) * 0.5f);
    if (part == 0 && c >= 64) {
        float4 qb = *(const float4*)(g_qb + (size_t)b * 64 + (c - 64));
        v.x += qb.x; v.y += qb.y; v.z += qb.z; v.w += qb.w;
    }
    *(float4*)(out + (size_t)idx * 128 + c) = v;
}

// ---------------- launch ----------------
extern "C" void kernel_launch(void* const* d_in, const int* in_sizes, int n_in,
                              void* d_out, int out_size) {
    const float* W_word   = (const float*)d_in[0];
    const float* W_query  = (const float*)d_in[1];
    const float* W_entity = (const float*)d_in[2];
    const float* Wq       = (const float*)d_in[3];
    const float* Wk       = (const float*)d_in[4];
    const float* Wv       = (const float*)d_in[5];
    const float* Wo       = (const float*)d_in[6];
    const int* qids   = (const int*)d_in[7];
    const int* rids   = (const int*)d_in[8];
    const int* pdst   = (const int*)d_in[9];
    const int* p_src  = (const int*)d_in[10];
    const int* p_dst  = (const int*)d_in[11];
    const int* p_qid  = (const int*)d_in[12];
    const int* users  = (const int*)d_in[13];
    const int* items  = (const int*)d_in[14];
    const int* negs   = (const int*)d_in[15];
    const int* qwords = (const int*)d_in[16];

    int NW = in_sizes[0] / 64;
    int Q = in_sizes[1] / 64;
    int N = in_sizes[2] / 64;
    int R = in_sizes[9];
    int E = in_sizes[10];
    int B = in_sizes[13];

    zero_kernel<<<4096, 256>>>(N);
    precompute_P<<<64, 256>>>(Wv, Wo);

    {
        int smem = 98304 + 8192;   // 106496 B
        cudaFuncSetAttribute(fuse_zqk, cudaFuncAttributeMaxDynamicSharedMemorySize, smem);
        fuse_zqk<<<296, 384, smem>>>(W_word, Wq, Wk, NW);
    }

    attn_kernel<<<1184, 256>>>(qids, rids, qwords, Q, R, B);

    profile_kernel<<<(R * 16 + 255) / 256, 256>>>(pdst, R);
    degi_kernel<<<(E + 255) / 256, 256>>>(p_src, p_dst, E);
    build_kernel<<<(N * 32 + 255) / 256, 256>>>(W_query, W_entity, Q, N);

    long long ethreads = (long long)E * 32;
    edge_kernel<<<(int)((ethreads + 255) / 256), 256>>>(p_src, p_dst, p_qid, E);

    output_kernel<<<(3 * B * 32 + 255) / 256, 256>>>(users, items, negs, B, (float*)d_out);
}

// round 8
// speedup vs baseline: 2.6196x; 1.4041x over previous
#include <cuda_runtime.h>
#include <math.h>
#include <stdint.h>

// Problem dimensions (fixed dataset; runtime values still read from in_sizes)
#define WORD_N   50000
#define QUERY_N  50000
#define ENT_N    100000
#define REV_N    100000
#define BATCH_N  1024
#define DWDIM    64
#define DDIM     128

typedef unsigned long long u64t;

// ---------------- scratch (static __device__, no allocation) ----------------
__device__ __align__(16) float g_hq[QUERY_N * DWDIM];
__device__ __align__(16) float g_hr[REV_N * DWDIM];
__device__ __align__(16) float g_qb[BATCH_N * DWDIM];
__device__ __align__(16) float g_enth[ENT_N * DWDIM];
__device__ __align__(16) float g_degp[ENT_N];
__device__ __align__(16) float g_degi[ENT_N];
__device__ __align__(16) float g_invs[ENT_N];
__device__ __align__(16) float g_ek[ENT_N * DDIM];
__device__ __align__(16) float g_qe0[QUERY_N * DDIM];
__device__ __align__(16) float g_agg[ENT_N * DDIM];
__device__ __align__(16) float g_P[4 * 64 * 64];        // P_h = Wv[:,h16] @ Wo[h16,:]
__device__ __align__(16) float g_QKW[WORD_N * 128];     // per word: [q(64) | k(64)]
__device__ __align__(16) float g_Z[WORD_N * 256];       // per word: [h0|h1|h2|h3] = x_w @ P_h
__device__ __align__(16) unsigned int g_bitmap[4096];   // needed-entity bitmap (100K bits)

// ---------------- helpers ----------------
__device__ __forceinline__ u64t pack1(float x) {
    u64t r; asm("mov.b64 %0, {%1,%1};" : "=l"(r) : "f"(x)); return r;
}
__device__ __forceinline__ u64t ffma2(u64t a, u64t b, u64t c) {
    u64t d; asm("fma.rn.f32x2 %0, %1, %2, %3;" : "=l"(d) : "l"(a), "l"(b), "l"(c));
    return d;
}
__device__ __forceinline__ void red_add_v4(float* p, float4 v) {
    asm volatile("red.global.add.v4.f32 [%0], {%1,%2,%3,%4};"
                 :: "l"(p), "f"(v.x), "f"(v.y), "f"(v.z), "f"(v.w) : "memory");
}

// ---------------- zero scratch ----------------
__global__ void zero_kernel(int N) {
    int g = blockIdx.x * blockDim.x + threadIdx.x;
    int stride = gridDim.x * blockDim.x;
    float4 z = make_float4(0.f, 0.f, 0.f, 0.f);
    int n_agg4 = N * 32;
    for (int i = g; i < n_agg4; i += stride) ((float4*)g_agg)[i] = z;
    int n_eh4 = N * 16;
    for (int i = g; i < n_eh4; i += stride) ((float4*)g_enth)[i] = z;
    int n4 = N / 4;
    for (int i = g; i < n4; i += stride) { ((float4*)g_degp)[i] = z; ((float4*)g_degi)[i] = z; }
    if (g < 4096) g_bitmap[g] = 0u;
}

// ---------------- precompute P_h = Wv[:, h*16:(h+1)*16] @ Wo[h*16:(h+1)*16, :] ----------------
__global__ void precompute_P(const float* __restrict__ Wv, const float* __restrict__ Wo) {
    int t = blockIdx.x * blockDim.x + threadIdx.x;
    if (t >= 4 * 64 * 64) return;
    int h = t >> 12, d = (t >> 6) & 63, c = t & 63;
    float s = 0.f;
    #pragma unroll
    for (int u = 0; u < 16; u++)
        s += Wv[d * 64 + h * 16 + u] * Wo[(h * 16 + u) * 64 + c];
    g_P[t] = s;
}

// ---------------- mark needed entities from users/items/negs ----------------
__global__ void mark_needed(const int* __restrict__ users, const int* __restrict__ items,
                            const int* __restrict__ negs, int B) {
    int g = blockIdx.x * blockDim.x + threadIdx.x;
    if (g >= 3 * B) return;
    int part = g / B, b = g % B;
    int r = (part == 0) ? users[b] : ((part == 1) ? items[b] : negs[b]);
    atomicOr(&g_bitmap[r >> 5], 1u << (r & 31));
}

// ---------------- fused Z + QK precompute:  [Z | Q | K](w) = x_w @ [P | Wq | Wk] ----------------
__global__ __launch_bounds__(384) void fuse_zqk(
    const float* __restrict__ W_word, const float* __restrict__ Wq,
    const float* __restrict__ Wk, int NW)
{
    extern __shared__ char sm[];
    float* sB = (float*)sm;                   // 64*384 floats = 98304 B
    u64t* sx2 = (u64t*)(sm + 98304);          // 64*16 u64 = 8192 B
    int t = threadIdx.x;

    for (int i = t; i < 24576; i += 384) {
        int d = i / 384, c = i % 384;
        float v;
        if (c < 256)      v = g_P[((c >> 6) << 12) + d * 64 + (c & 63)];
        else if (c < 320) v = Wq[d * 64 + (c - 256)];
        else              v = Wk[d * 64 + (c - 320)];
        sB[d * 384 + c] = v;
    }

    int wgroup = t / 192;            // 0 or 1 -> words 0..7 / 8..15 of tile
    int cpair = t % 192;
    int c0 = cpair * 2;
    int ntiles = (NW + 15) / 16;

    for (int tile = blockIdx.x; tile < ntiles; tile += gridDim.x) {
        __syncthreads();
        for (int i = t; i < 1024; i += 384) {
            int wi = i >> 6, d = i & 63;
            int w = tile * 16 + wi;
            float v = W_word[(size_t)(w < NW ? w : 0) * 64 + d];
            sx2[d * 16 + wi] = pack1(v);
        }
        __syncthreads();

        u64t acc0 = 0ULL, acc1 = 0ULL, acc2 = 0ULL, acc3 = 0ULL;
        u64t acc4 = 0ULL, acc5 = 0ULL, acc6 = 0ULL, acc7 = 0ULL;
        #pragma unroll 4
        for (int d = 0; d < 64; d++) {
            u64t b2 = *(const u64t*)(sB + d * 384 + c0);
            const u64t* xr = sx2 + d * 16 + wgroup * 8;
            acc0 = ffma2(xr[0], b2, acc0);
            acc1 = ffma2(xr[1], b2, acc1);
            acc2 = ffma2(xr[2], b2, acc2);
            acc3 = ffma2(xr[3], b2, acc3);
            acc4 = ffma2(xr[4], b2, acc4);
            acc5 = ffma2(xr[5], b2, acc5);
            acc6 = ffma2(xr[6], b2, acc6);
            acc7 = ffma2(xr[7], b2, acc7);
        }
        int wbase = tile * 16 + wgroup * 8;
        size_t stride_out;
        float* outb;
        if (c0 < 256)      { outb = g_Z + (size_t)wbase * 256 + c0;              stride_out = 256; }
        else if (c0 < 320) { outb = g_QKW + (size_t)wbase * 128 + (c0 - 256);    stride_out = 128; }
        else               { outb = g_QKW + (size_t)wbase * 128 + 64 + (c0 - 320); stride_out = 128; }
        int nvalid = NW - wbase;
        if (nvalid >= 8) {
            *(u64t*)(outb)                  = acc0;
            *(u64t*)(outb + stride_out)     = acc1;
            *(u64t*)(outb + stride_out * 2) = acc2;
            *(u64t*)(outb + stride_out * 3) = acc3;
            *(u64t*)(outb + stride_out * 4) = acc4;
            *(u64t*)(outb + stride_out * 5) = acc5;
            *(u64t*)(outb + stride_out * 6) = acc6;
            *(u64t*)(outb + stride_out * 7) = acc7;
        } else if (nvalid > 0) {
            if (nvalid > 0) *(u64t*)(outb)                  = acc0;
            if (nvalid > 1) *(u64t*)(outb + stride_out)     = acc1;
            if (nvalid > 2) *(u64t*)(outb + stride_out * 2) = acc2;
            if (nvalid > 3) *(u64t*)(outb + stride_out * 3) = acc3;
            if (nvalid > 4) *(u64t*)(outb + stride_out * 4) = acc4;
            if (nvalid > 5) *(u64t*)(outb + stride_out * 5) = acc5;
            if (nvalid > 6) *(u64t*)(outb + stride_out * 6) = acc6;
        }
    }
}

// ---------------- attention: scores + softmax + Z-combine (one warp per doc) ----------------
__global__ __launch_bounds__(256)
void attn_kernel(const int* __restrict__ qids, const int* __restrict__ rids,
                 const int* __restrict__ bids, int Q, int R, int B)
{
    int tid = threadIdx.x, lane = tid & 31, warp = tid >> 5;
    int T = Q + R + B;
    int hh = lane >> 3, jj = lane & 7;

    for (int doc = blockIdx.x * 8 + warp; doc < T; doc += gridDim.x * 8) {
        const int* ids; float* outp;
        if (doc < Q)          { ids = qids + (size_t)doc * 8;       outp = g_hq + (size_t)doc * 64; }
        else if (doc < Q + R) { int r = doc - Q; ids = rids + (size_t)r * 8; outp = g_hr + (size_t)r * 64; }
        else                  { int b = doc - Q - R; ids = bids + (size_t)b * 8; outp = g_qb + (size_t)b * 64; }

        int myid = ids[jj];

        const float4* kp = (const float4*)(g_QKW + (size_t)myid * 128 + 64 + hh * 16);
        float4 k0 = __ldg(kp), k1 = __ldg(kp + 1), k2 = __ldg(kp + 2), k3 = __ldg(kp + 3);

        float a_acc = 0.f;
        #pragma unroll
        for (int l = 0; l < 8; l++) {
            int idl = __shfl_sync(0xffffffffu, myid, l);
            const float4* qp = (const float4*)(g_QKW + (size_t)idl * 128 + hh * 16);
            float4 q0 = __ldg(qp), q1 = __ldg(qp + 1), q2 = __ldg(qp + 2), q3 = __ldg(qp + 3);
            float s = q0.x*k0.x + q0.y*k0.y + q0.z*k0.z + q0.w*k0.w
                    + q1.x*k1.x + q1.y*k1.y + q1.z*k1.z + q1.w*k1.w
                    + q2.x*k2.x + q2.y*k2.y + q2.z*k2.z + q2.w*k2.w
                    + q3.x*k3.x + q3.y*k3.y + q3.z*k3.z + q3.w*k3.w;
            float e = __expf(s * 0.25f);
            float t = e;
            t += __shfl_xor_sync(0xffffffffu, t, 1);
            t += __shfl_xor_sync(0xffffffffu, t, 2);
            t += __shfl_xor_sync(0xffffffffu, t, 4);
            a_acc += e * __frcp_rn(t);
        }
        a_acc *= 0.125f;

        int c0 = lane * 2;
        u64t o = 0;
        #pragma unroll
        for (int j = 0; j < 8; j++) {
            int idz = __shfl_sync(0xffffffffu, myid, j);
            const float* zr = g_Z + (size_t)idz * 256 + c0;
            #pragma unroll
            for (int h = 0; h < 4; h++) {
                float av = __shfl_sync(0xffffffffu, a_acc, h * 8 + j);
                o = ffma2(pack1(av), __ldg((const u64t*)(zr + h * 64)), o);
            }
        }
        *(u64t*)(outp + c0) = o;
        __syncwarp();
    }
}

// ---------------- profile aggregation: ent_h += h_review, deg_p += 1 ----------------
__global__ void profile_kernel(const int* __restrict__ pdst, int R) {
    int g = blockIdx.x * blockDim.x + threadIdx.x;
    int r = g >> 4, q = g & 15;
    if (r >= R) return;
    int d = pdst[r];
    float4 v = *(const float4*)(g_hr + (size_t)r * 64 + q * 4);
    red_add_v4(g_enth + (size_t)d * 64 + q * 4, v);
    if (q == 0) atomicAdd(g_degp + d, 1.0f);
}

// ---------------- interaction degree ----------------
__global__ void degi_kernel(const int* __restrict__ ps, const int* __restrict__ pd, int E) {
    int g = blockIdx.x * blockDim.x + threadIdx.x;
    if (g >= E) return;
    atomicAdd(g_degi + ps[g], 1.0f);
    atomicAdd(g_degi + pd[g], 1.0f);
}

// ---------------- build e_0, q_e0, inv_sqrt ----------------
__global__ void build_kernel(const float* __restrict__ W_query,
                             const float* __restrict__ W_entity, int Q, int N) {
    int g = blockIdx.x * blockDim.x + threadIdx.x;
    int n = g >> 5, lane = g & 31;
    if (n >= N) return;
    int c = lane * 4;
    if (lane == 0) g_invs[n] = 1.0f / sqrtf(fmaxf(g_degi[n], 1.0f));
    float4 v;
    if (c < 64) {
        v = *(const float4*)(W_entity + (size_t)n * 64 + c);
    } else {
        float invdp = 1.0f / fmaxf(g_degp[n], 1.0f);
        float4 hv = *(const float4*)(g_enth + (size_t)n * 64 + (c - 64));
        v = make_float4(hv.x * invdp, hv.y * invdp, hv.z * invdp, hv.w * invdp);
    }
    *(float4*)(g_ek + (size_t)n * 128 + c) = v;
    if (n < Q) {
        float4 u;
        if (c < 64) u = *(const float4*)(W_query + (size_t)n * 64 + c);
        else        u = *(const float4*)(g_hq + (size_t)n * 64 + (c - 64));
        *(float4*)(g_qe0 + (size_t)n * 128 + c) = u;
    }
}

// ---------------- gated edge conv: warp per edge, scatter only to needed rows ----------------
__global__ void edge_gated_kernel(const int* __restrict__ ps, const int* __restrict__ pd,
                                  const int* __restrict__ pq, int E) {
    long long g = (long long)blockIdx.x * blockDim.x + threadIdx.x;
    int e = (int)(g >> 5);
    int lane = (int)(g & 31);
    if (e >= E) return;
    int src = __ldg(ps + e), dst = __ldg(pd + e);
    bool fwd = (g_bitmap[dst >> 5] >> (dst & 31)) & 1u;   // dst needed -> fwd msg matters
    bool rev = (g_bitmap[src >> 5] >> (src & 31)) & 1u;   // src needed -> rev msg matters
    if (!(fwd | rev)) return;
    int c = lane * 4;
    if (fwd) {
        int qid = __ldg(pq + e);
        float is = g_invs[src];
        float4 es = *(const float4*)(g_ek + (size_t)src * 128 + c);
        float4 qv = *(const float4*)(g_qe0 + (size_t)qid * 128 + c);
        float4 m = make_float4(es.x + qv.x * is, es.y + qv.y * is,
                               es.z + qv.z * is, es.w + qv.w * is);
        red_add_v4(g_agg + (size_t)dst * 128 + c, m);
    }
    if (rev) {
        float id = g_invs[dst];
        float4 ed = *(const float4*)(g_ek + (size_t)dst * 128 + c);
        float4 m2 = make_float4(ed.x * id, ed.y * id, ed.z * id, ed.w * id);
        red_add_v4(g_agg + (size_t)src * 128 + c, m2);
    }
}

// ---------------- output: gather e = (e0 + agg*inv)/2 at users/items/negs ----------------
__global__ void output_kernel(const int* __restrict__ users, const int* __restrict__ items,
                              const int* __restrict__ negs, int B, float* __restrict__ out) {
    int g = blockIdx.x * blockDim.x + threadIdx.x;
    int idx = g >> 5, lane = g & 31;
    if (idx >= 3 * B) return;
    int part = idx / B, b = idx % B;
    int r = (part == 0) ? users[b] : ((part == 1) ? items[b] : negs[b]);
    int c = lane * 4;
    float inv = g_invs[r];
    float4 ev = *(const float4*)(g_ek + (size_t)r * 128 + c);
    float4 av = *(const float4*)(g_agg + (size_t)r * 128 + c);
    float4 v = make_float4((ev.x + av.x * inv) * 0.5f, (ev.y + av.y * inv) * 0.5f,
                           (ev.z + av.z * inv) * 0.5f, (ev.w + av.w * inv) * 0.5f);
    if (part == 0 && c >= 64) {
        float4 qb = *(const float4*)(g_qb + (size_t)b * 64 + (c - 64));
        v.x += qb.x; v.y += qb.y; v.z += qb.z; v.w += qb.w;
    }
    *(float4*)(out + (size_t)idx * 128 + c) = v;
}

// ---------------- launch ----------------
extern "C" void kernel_launch(void* const* d_in, const int* in_sizes, int n_in,
                              void* d_out, int out_size) {
    const float* W_word   = (const float*)d_in[0];
    const float* W_query  = (const float*)d_in[1];
    const float* W_entity = (const float*)d_in[2];
    const float* Wq       = (const float*)d_in[3];
    const float* Wk       = (const float*)d_in[4];
    const float* Wv       = (const float*)d_in[5];
    const float* Wo       = (const float*)d_in[6];
    const int* qids   = (const int*)d_in[7];
    const int* rids   = (const int*)d_in[8];
    const int* pdst   = (const int*)d_in[9];
    const int* p_src  = (const int*)d_in[10];
    const int* p_dst  = (const int*)d_in[11];
    const int* p_qid  = (const int*)d_in[12];
    const int* users  = (const int*)d_in[13];
    const int* items  = (const int*)d_in[14];
    const int* negs   = (const int*)d_in[15];
    const int* qwords = (const int*)d_in[16];

    int NW = in_sizes[0] / 64;
    int Q = in_sizes[1] / 64;
    int N = in_sizes[2] / 64;
    int R = in_sizes[9];
    int E = in_sizes[10];
    int B = in_sizes[13];

    zero_kernel<<<4096, 256>>>(N);
    precompute_P<<<64, 256>>>(Wv, Wo);
    mark_needed<<<(3 * B + 255) / 256, 256>>>(users, items, negs, B);

    {
        int smem = 98304 + 8192;   // 106496 B
        cudaFuncSetAttribute(fuse_zqk, cudaFuncAttributeMaxDynamicSharedMemorySize, smem);
        fuse_zqk<<<296, 384, smem>>>(W_word, Wq, Wk, NW);
    }

    attn_kernel<<<1184, 256>>>(qids, rids, qwords, Q, R, B);

    profile_kernel<<<(R * 16 + 255) / 256, 256>>>(pdst, R);
    degi_kernel<<<(E + 255) / 256, 256>>>(p_src, p_dst, E);
    build_kernel<<<(N * 32 + 255) / 256, 256>>>(W_query, W_entity, Q, N);

    long long ethreads = (long long)E * 32;
    edge_gated_kernel<<<(int)((ethreads + 255) / 256), 256>>>(p_src, p_dst, p_qid, E);

    output_kernel<<<(3 * B * 32 + 255) / 256, 256>>>(users, items, negs, B, (float*)d_out);
}